// round 9
// baseline (speedup 1.0000x reference)
#include <cuda_runtime.h>
#include <stdint.h>

// XNOR binarized linear, two-stage streaming pipeline.
//   Stage 1: pack x sign bits  (256MB read -> 8MB write, pure streaming)
//   Stage 2: popc compute      (8MB L2-hot read -> 256MB write, compute+store
//                               interleaved every iteration)
// This removes the mem-phase/compute-phase serialization that capped all
// fused variants at ~150us (no pipe above 52% there).

constexpr int NROWS = 262144;
constexpr int DIM   = 256;
constexpr int WPR   = 8;

constexpr int WARPS      = 8;
constexpr int BLOCK_ROWS = 32 * WARPS;            // 256 rows per block
constexpr int NBLK       = NROWS / BLOCK_ROWS;    // 1024 blocks

__device__ uint32_t g_wbits[DIM * WPR];           // packed weights (8 KB)
__device__ uint32_t g_xbits[NROWS * WPR];         // packed activations (8 MB)

// ---------------------------------------------------------------------------
// Pre-kernel: pack weight sign bits (one warp per output row).
// Word (h*4+c), bit L  <->  element h*128 + 4L + c. Matches x packing below.
// ---------------------------------------------------------------------------
__global__ void pack_w_kernel(const float* __restrict__ w) {
    int warp = (blockIdx.x * blockDim.x + threadIdx.x) >> 5;
    int lane = threadIdx.x & 31;
    if (warp >= DIM) return;
    const float4* row = reinterpret_cast<const float4*>(w) + (size_t)warp * (DIM / 4);
#pragma unroll
    for (int h = 0; h < 2; ++h) {
        float4 v = row[h * 32 + lane];
        uint32_t m0 = __ballot_sync(0xFFFFFFFFu, v.x < 0.0f);
        uint32_t m1 = __ballot_sync(0xFFFFFFFFu, v.y < 0.0f);
        uint32_t m2 = __ballot_sync(0xFFFFFFFFu, v.z < 0.0f);
        uint32_t m3 = __ballot_sync(0xFFFFFFFFu, v.w < 0.0f);
        if (lane == 0) {
            *reinterpret_cast<uint4*>(&g_wbits[warp * WPR + h * 4]) =
                make_uint4(m0, m1, m2, m3);
        }
    }
}

// ---------------------------------------------------------------------------
// Stage 1: pack x. Each warp packs 32 rows; lane r keeps row r, then stores
// its 32B packed row (two STG.128, contiguous 1KB per warp).
// ---------------------------------------------------------------------------
__global__ void __launch_bounds__(256, 6)
pack_x_kernel(const float* __restrict__ x) {
    const int warp = threadIdx.x >> 5;
    const int lane = threadIdx.x & 31;
    const int rowBase = (blockIdx.x * WARPS + warp) * 32;

    const float4* rp = reinterpret_cast<const float4*>(x) +
                       (size_t)rowBase * (DIM / 4);

    uint32_t mb0, mb1, mb2, mb3, mb4, mb5, mb6, mb7;

    float4 c0 = rp[lane];       float4 c1 = rp[32 + lane];
    float4 d0 = rp[64 + lane];  float4 d1 = rp[96 + lane];
#pragma unroll
    for (int r = 0; r < 32; ++r) {
        const int rn = (r + 2 < 32) ? r + 2 : 31;
        float4 e0 = rp[rn * 64 + lane];
        float4 e1 = rp[rn * 64 + 32 + lane];

        uint32_t b0 = __ballot_sync(0xFFFFFFFFu, c0.x < 0.0f);
        uint32_t b1 = __ballot_sync(0xFFFFFFFFu, c0.y < 0.0f);
        uint32_t b2 = __ballot_sync(0xFFFFFFFFu, c0.z < 0.0f);
        uint32_t b3 = __ballot_sync(0xFFFFFFFFu, c0.w < 0.0f);
        uint32_t b4 = __ballot_sync(0xFFFFFFFFu, c1.x < 0.0f);
        uint32_t b5 = __ballot_sync(0xFFFFFFFFu, c1.y < 0.0f);
        uint32_t b6 = __ballot_sync(0xFFFFFFFFu, c1.z < 0.0f);
        uint32_t b7 = __ballot_sync(0xFFFFFFFFu, c1.w < 0.0f);
        if (lane == r) {
            mb0 = b0; mb1 = b1; mb2 = b2; mb3 = b3;
            mb4 = b4; mb5 = b5; mb6 = b6; mb7 = b7;
        }
        c0 = d0; c1 = d1; d0 = e0; d1 = e1;
    }

    uint4* xb = reinterpret_cast<uint4*>(&g_xbits[(size_t)(rowBase + lane) * WPR]);
    xb[0] = make_uint4(mb0, mb1, mb2, mb3);
    xb[1] = make_uint4(mb4, mb5, mb6, mb7);
}

// ---------------------------------------------------------------------------
// Stage 2: compute. Lane L holds packed row rowBase+L (2 LDG.128, L2-hot).
// Loop over all 256 outputs, weights broadcast from smem; results staged in
// smem (stride-17) and written out transposed as coalesced STG.128.
// ---------------------------------------------------------------------------
__global__ void __launch_bounds__(256, 5)
xnor_compute_kernel(const float* __restrict__ scale,
                    float* __restrict__ out) {
    __shared__ uint32_t sw[DIM * WPR];               // weights, 8 KB
    __shared__ float    ss[DIM];                     // scales, 1 KB
    __shared__ uint32_t stage[WARPS][32][17];        // transpose stage

    const int tid  = threadIdx.x;
    const int warp = tid >> 5;
    const int lane = tid & 31;
    const int rowBase = blockIdx.x * BLOCK_ROWS + warp * 32;

    // weights + scales into smem (once per block)
    {
        const uint4* gw = reinterpret_cast<const uint4*>(g_wbits);
        uint4* swv = reinterpret_cast<uint4*>(sw);
        swv[tid]       = gw[tid];
        swv[tid + 256] = gw[tid + 256];
        ss[tid] = scale[tid];
    }

    // packed row for this lane (L2-hot: written by stage 1)
    const uint4* xb = reinterpret_cast<const uint4*>(
        &g_xbits[(size_t)(rowBase + lane) * WPR]);
    const uint4 rlo = xb[0];
    const uint4 rhi = xb[1];
    const uint32_t mb0 = rlo.x, mb1 = rlo.y, mb2 = rlo.z, mb3 = rlo.w;
    const uint32_t mb4 = rhi.x, mb5 = rhi.y, mb6 = rhi.z, mb7 = rhi.w;

    __syncthreads();   // weights/scales visible

    constexpr uint32_t MAGIC256 = 0x4B400000u + 256u;   // 2^23*1.5 + 256

#pragma unroll 1
    for (int och = 0; och < 16; ++och) {
#pragma unroll
        for (int oo = 0; oo < 16; ++oo) {
            const int o = och * 16 + oo;
            const uint4 w0 = *reinterpret_cast<const uint4*>(&sw[o * WPR]);
            const uint4 w1 = *reinterpret_cast<const uint4*>(&sw[o * WPR + 4]);
            int p = __popc(mb0 ^ w0.x) + __popc(mb1 ^ w0.y) +
                    __popc(mb2 ^ w0.z) + __popc(mb3 ^ w0.w) +
                    __popc(mb4 ^ w1.x) + __popc(mb5 ^ w1.y) +
                    __popc(mb6 ^ w1.z) + __popc(mb7 ^ w1.w);
            uint32_t t = MAGIC256 - 2u * (uint32_t)p;        // IMAD
            float y = (__uint_as_float(t) - 12582912.0f) * ss[o];  // exact
            stage[warp][lane][oo] = __float_as_uint(y);      // conflict-free
        }
        __syncwarp();

        // transpose-out: 4 phases, each 8 rows x 16B chunks, STG.128
#pragma unroll
        for (int ph = 0; ph < 4; ++ph) {
            const int r = ph * 8 + (lane >> 2);
            const int c = (lane & 3) * 4;
            uint4 v;
            v.x = stage[warp][r][c];
            v.y = stage[warp][r][c + 1];
            v.z = stage[warp][r][c + 2];
            v.w = stage[warp][r][c + 3];
            *reinterpret_cast<uint4*>(out + (size_t)(rowBase + r) * DIM +
                                      och * 16 + c) = v;
        }
        __syncwarp();
    }
}

// ---------------------------------------------------------------------------
// kernel_launch: d_in[0]=x [N,256] f32, d_in[1]=weight [256,256] f32,
//                d_in[2]=scale [1,256] f32; d_out = y [N,256] f32.
// ---------------------------------------------------------------------------
extern "C" void kernel_launch(void* const* d_in, const int* in_sizes, int n_in,
                              void* d_out, int out_size) {
    const float* x      = (const float*)d_in[0];
    const float* weight = (const float*)d_in[1];
    const float* scale  = (const float*)d_in[2];
    float* out          = (float*)d_out;
    (void)in_sizes; (void)n_in; (void)out_size;

    pack_w_kernel<<<32, 256>>>(weight);
    pack_x_kernel<<<NBLK, 256>>>(x);
    xnor_compute_kernel<<<NBLK, 256>>>(scale, out);
}

// round 10
// speedup vs baseline: 1.2430x; 1.2430x over previous
#include <cuda_runtime.h>
#include <stdint.h>

// XNOR binarized linear, warp-broadcast popc + CSA compression.
// y[n,o] = (256 - 2*popc(xbits[n] ^ wbits[o])) * scale[o]
//
// POPC is quarter-rate (16/clk/SM); it is the hidden wall at ~120us for the
// naive 8-popc/output form. CSA (carry-save) compression replaces 8 POPCs
// with 5 POPCs + 8 full-rate LOP3s per output:
//   sum popc(y0..y7) = popc(a1)+popc(a2)+popc(a3) + 2*popc(t) + 4*popc(d)
// Structure otherwise identical to the best kernel (R5).

constexpr int NROWS = 262144;
constexpr int DIM   = 256;   // IN == OUT
constexpr int WPR   = 8;     // packed words per row

constexpr int CHUNK_ROWS = 128;                 // rows per block chunk (4 warps x 32)
constexpr int NCHUNK     = NROWS / CHUNK_ROWS;  // 2048
constexpr int GRID       = 592;                 // 148 SMs x 4 blocks

__device__ uint32_t g_wbits[DIM * WPR];

__device__ __forceinline__ uint32_t maj3(uint32_t a, uint32_t b, uint32_t c) {
    return (a & b) | (c & (a | b));              // single LOP3 (0xE8)
}
__device__ __forceinline__ uint32_t xor3(uint32_t a, uint32_t b, uint32_t c) {
    return a ^ b ^ c;                            // single LOP3 (0x96)
}

// ---------------------------------------------------------------------------
// Pre-kernel: pack weight sign bits (one warp per output row).
// Word (h*4+c), bit L  <->  element h*128 + 4L + c. Matches x packing below.
// ---------------------------------------------------------------------------
__global__ void pack_w_kernel(const float* __restrict__ w) {
    int warp = (blockIdx.x * blockDim.x + threadIdx.x) >> 5;
    int lane = threadIdx.x & 31;
    if (warp >= DIM) return;
    const float4* row = reinterpret_cast<const float4*>(w) + (size_t)warp * (DIM / 4);
#pragma unroll
    for (int h = 0; h < 2; ++h) {
        float4 v = row[h * 32 + lane];
        uint32_t m0 = __ballot_sync(0xFFFFFFFFu, v.x < 0.0f);
        uint32_t m1 = __ballot_sync(0xFFFFFFFFu, v.y < 0.0f);
        uint32_t m2 = __ballot_sync(0xFFFFFFFFu, v.z < 0.0f);
        uint32_t m3 = __ballot_sync(0xFFFFFFFFu, v.w < 0.0f);
        if (lane == 0) {
            *reinterpret_cast<uint4*>(&g_wbits[warp * WPR + h * 4]) =
                make_uint4(m0, m1, m2, m3);
        }
    }
}

// ---------------------------------------------------------------------------
// Main kernel: 128 threads (4 warps), grid-stride over 128-row chunks.
// ---------------------------------------------------------------------------
__global__ void __launch_bounds__(128, 4)
xnor_csa_kernel(const float* __restrict__ x,
                const float* __restrict__ scale,
                float* __restrict__ out) {
    const int warp = threadIdx.x >> 5;
    const int lane = threadIdx.x & 31;

    // Hoist weights + scale for this lane's 8 output columns.
    uint4 wlo[8], whi[8];
    float S[8];
#pragma unroll
    for (int j = 0; j < 8; ++j) {
        int o = j * 32 + lane;
        wlo[j] = *reinterpret_cast<const uint4*>(&g_wbits[o * WPR]);
        whi[j] = *reinterpret_cast<const uint4*>(&g_wbits[o * WPR + 4]);
        S[j] = scale[o];
    }

    constexpr uint32_t MAGIC256 = 0x4B400000u + 256u;   // 2^23*1.5 + 256

    const float4* x4 = reinterpret_cast<const float4*>(x);

    for (int ch = blockIdx.x; ch < NCHUNK; ch += gridDim.x) {
        const int row0 = ch * CHUNK_ROWS + warp * 32;
        const float4* rp = x4 + (size_t)row0 * (DIM / 4);
        float* orow = out + (size_t)row0 * DIM + lane;

        // prefetch first row
        float4 c0 = rp[lane];
        float4 c1 = rp[32 + lane];

#pragma unroll 2
        for (int r = 0; r < 32; ++r) {
            // prefetch next row (clamped on last iteration)
            const float4* np = rp + (size_t)(r + 1 < 32 ? r + 1 : r) * (DIM / 4);
            float4 n0 = np[lane];
            float4 n1 = np[32 + lane];

            // transpose row signs into 8 words, broadcast to all lanes
            uint32_t b0 = __ballot_sync(0xFFFFFFFFu, c0.x < 0.0f);
            uint32_t b1 = __ballot_sync(0xFFFFFFFFu, c0.y < 0.0f);
            uint32_t b2 = __ballot_sync(0xFFFFFFFFu, c0.z < 0.0f);
            uint32_t b3 = __ballot_sync(0xFFFFFFFFu, c0.w < 0.0f);
            uint32_t b4 = __ballot_sync(0xFFFFFFFFu, c1.x < 0.0f);
            uint32_t b5 = __ballot_sync(0xFFFFFFFFu, c1.y < 0.0f);
            uint32_t b6 = __ballot_sync(0xFFFFFFFFu, c1.z < 0.0f);
            uint32_t b7 = __ballot_sync(0xFFFFFFFFu, c1.w < 0.0f);

            // 8 independent output-group chains (ILP), CSA-compressed popc
#pragma unroll
            for (int j = 0; j < 8; ++j) {
                uint32_t y0 = b0 ^ wlo[j].x;
                uint32_t y1 = b1 ^ wlo[j].y;
                uint32_t y2 = b2 ^ wlo[j].z;
                uint32_t y3 = b3 ^ wlo[j].w;
                uint32_t y4 = b4 ^ whi[j].x;
                uint32_t y5 = b5 ^ whi[j].y;
                uint32_t y6 = b6 ^ whi[j].z;
                uint32_t y7 = b7 ^ whi[j].w;

                // CSA tree: 8 ones -> 3 ones + 3 twos -> (+carry level)
                uint32_t a1 = xor3(y0, y1, y2);
                uint32_t k1 = maj3(y0, y1, y2);
                uint32_t a2 = xor3(y3, y4, y5);
                uint32_t k2 = maj3(y3, y4, y5);
                uint32_t a3 = y6 ^ y7;
                uint32_t k3 = y6 & y7;
                uint32_t t  = xor3(k1, k2, k3);      // weight-2 sum
                uint32_t d  = maj3(k1, k2, k3);      // weight-4 carry

                int p = __popc(a1) + __popc(a2) + __popc(a3)
                      + 2 * __popc(t) + 4 * __popc(d);

                // exact epilogue: fd = float(256-2p) exactly, single rounding
                uint32_t tt = MAGIC256 - 2u * (uint32_t)p;      // IMAD
                float fd = __uint_as_float(tt) - 12582912.0f;   // FADD (exact)
                orow[j * 32] = fd * S[j];                       // FMUL
            }

            c0 = n0; c1 = n1;
            orow += DIM;
        }
    }
}

// ---------------------------------------------------------------------------
// kernel_launch: d_in[0]=x [N,256] f32, d_in[1]=weight [256,256] f32,
//                d_in[2]=scale [1,256] f32; d_out = y [N,256] f32.
// ---------------------------------------------------------------------------
extern "C" void kernel_launch(void* const* d_in, const int* in_sizes, int n_in,
                              void* d_out, int out_size) {
    const float* x      = (const float*)d_in[0];
    const float* weight = (const float*)d_in[1];
    const float* scale  = (const float*)d_in[2];
    float* out          = (float*)d_out;
    (void)in_sizes; (void)n_in; (void)out_size;

    pack_w_kernel<<<32, 256>>>(weight);
    xnor_csa_kernel<<<GRID, 128>>>(x, scale, out);
}